// round 8
// baseline (speedup 1.0000x reference)
#include <cuda_runtime.h>
#include <cuda_bf16.h>

#define IMG_W 1024
#define IMG_H 1024
#define KS 15
#define NB 32

// Input tile staged in smem: x covers [bx*256-8, bx*256+264) = 272 floats,
// y covers [by*16-7, by*16+23) = 30 rows. Zero-padded outside the image.
#define TILE_W 272
#define TILE_H 30
#define SMEM_BYTES (512 + TILE_W * TILE_H * 4)

typedef unsigned long long u64;

// ---- packed fp32x2 helpers (Blackwell, PTX-only) ----
__device__ __forceinline__ u64 pack2(float lo, float hi) {
    u64 r;
    asm("mov.b64 %0, {%1, %2};" : "=l"(r) : "f"(lo), "f"(hi));
    return r;
}
__device__ __forceinline__ void unpack2(u64 v, float& lo, float& hi) {
    asm("mov.b64 {%0, %1}, %2;" : "=f"(lo), "=f"(hi) : "l"(v));
}
__device__ __forceinline__ void fma2(u64& d, u64 a, u64 b) {
    asm("fma.rn.f32x2 %0, %1, %2, %3;" : "=l"(d) : "l"(a), "l"(b), "l"(d));
}
__device__ __forceinline__ u64 add2(u64 a, u64 b) {
    u64 r;
    asm("add.rn.f32x2 %0, %1, %2;" : "=l"(r) : "l"(a), "l"(b));
    return r;
}

// Thread: 4 px (two f32x2 pairs) x 4 output rows. Block 256 thr = 8 warps:
// 2 in x, 4 in y. Block tile: 256 px * 16 rows. Grid (4, 64, 32).
// Weights (dx+dy folded Airy symmetry): 8 rows x 8 (w,w) pairs in smem.
// __launch_bounds__(256, 3): 85-reg cap -> 3 CTAs/SM = 24 warps (37.5% occ).
__global__ __launch_bounds__(256, 3) void stem_conv_roll(
    const float* __restrict__ in, const float* __restrict__ kern,
    const int* __restrict__ shifts, float* __restrict__ out)
{
    extern __shared__ char dynsmem[];
    u64*   sk  = reinterpret_cast<u64*>(dynsmem);          // 64 * 8B = 512B
    float* sIn = reinterpret_cast<float*>(dynsmem + 512);  // [TILE_H][TILE_W]

    const int tid = threadIdx.x;
    const int b   = blockIdx.z;
    const float* img = in + (size_t)b * (IMG_H * IMG_W);

    // Folded weights: sk[wr*8 + e] = (w,w), w = k[wr][7+e], wr = 0..7.
    if (tid < 64) {
        int wr = tid >> 3, e = tid & 7;
        float w = kern[wr * KS + 7 + e];
        sk[tid] = pack2(w, w);
    }

    // ---- Stage input tile (float4 granularity, zero-padded) ----
    const int gxb = blockIdx.x * 256 - 8;   // (gxb*4B) is 16B-aligned
    const int gyb = blockIdx.y * 16 - 7;
    #pragma unroll
    for (int idx = tid; idx < TILE_H * (TILE_W / 4); idx += 256) {
        const int ry  = idx / (TILE_W / 4);
        const int rx4 = idx - ry * (TILE_W / 4);
        const int gy  = gyb + ry;
        const int gx  = gxb + rx4 * 4;
        float4 v = make_float4(0.f, 0.f, 0.f, 0.f);
        if (gy >= 0 && gy < IMG_H) {
            const float* rowp = img + (size_t)gy * IMG_W;
            if (gx >= 0 && gx <= IMG_W - 4) {
                v = *reinterpret_cast<const float4*>(rowp + gx);
            } else {
                if (gx + 0 >= 0 && gx + 0 < IMG_W) v.x = rowp[gx + 0];
                if (gx + 1 >= 0 && gx + 1 < IMG_W) v.y = rowp[gx + 1];
                if (gx + 2 >= 0 && gx + 2 < IMG_W) v.z = rowp[gx + 2];
                if (gx + 3 >= 0 && gx + 3 < IMG_W) v.w = rowp[gx + 3];
            }
        }
        *reinterpret_cast<float4*>(sIn + ry * TILE_W + rx4 * 4) = v;
    }
    __syncthreads();

    const int lane = tid & 31;
    const int warp = tid >> 5;
    const int wx = warp & 1;
    const int wy = warp >> 1;
    const int xl = wx * 128 + lane * 4;       // local x of first px (mult of 4)
    const int x0 = blockIdx.x * 256 + xl;
    const int y0 = blockIdx.y * 16 + wy * 4;

    u64 acc0[4], acc1[4];
    #pragma unroll
    for (int r = 0; r < 4; ++r) { acc0[r] = 0ull; acc1[r] = 0ull; }

    // ga[j] = tile[wy*4 + g][xl + j], j = 0..19 (zero-padded image window)
    const float* tbase = sIn + wy * 4 * TILE_W + xl;

    #pragma unroll
    for (int g = 0; g < 18; ++g) {
        const float* trow = tbase + g * TILE_W;
        float ga[20];
        #pragma unroll
        for (int v = 0; v < 5; ++v) {
            float4 t = *reinterpret_cast<const float4*>(trow + 4 * v);
            ga[4*v+0] = t.x; ga[4*v+1] = t.y; ga[4*v+2] = t.z; ga[4*v+3] = t.w;
        }

        // Horizontal folds for pair0 (center ga[8],ga[9]) and pair1 (ga[10],ga[11]).
        u64 h0[8], h1[8];
        h0[0] = pack2(ga[8], ga[9]);
        h0[1] = pack2(ga[7] + ga[9],  ga[8] + ga[10]);
        h0[2] = add2(pack2(ga[6],  ga[7]),  pack2(ga[10], ga[11]));
        h0[3] = pack2(ga[5] + ga[11], ga[6] + ga[12]);
        h0[4] = add2(pack2(ga[4],  ga[5]),  pack2(ga[12], ga[13]));
        h0[5] = pack2(ga[3] + ga[13], ga[4] + ga[14]);
        h0[6] = add2(pack2(ga[2],  ga[3]),  pack2(ga[14], ga[15]));
        h0[7] = pack2(ga[1] + ga[15], ga[2] + ga[16]);

        h1[0] = pack2(ga[10], ga[11]);
        h1[1] = pack2(ga[9]  + ga[11], ga[10] + ga[12]);
        h1[2] = add2(pack2(ga[8],  ga[9]),  pack2(ga[12], ga[13]));
        h1[3] = pack2(ga[7]  + ga[13], ga[8]  + ga[14]);
        h1[4] = add2(pack2(ga[6],  ga[7]),  pack2(ga[14], ga[15]));
        h1[5] = pack2(ga[5]  + ga[15], ga[6]  + ga[16]);
        h1[6] = add2(pack2(ga[4],  ga[5]),  pack2(ga[16], ga[17]));
        h1[7] = pack2(ga[3]  + ga[17], ga[4]  + ga[18]);

        // dy = g - r in [0,14]; folded weight row wr = min(dy, 14-dy).
        #pragma unroll
        for (int r = 0; r < 4; ++r) {
            const int dy = g - r;                 // compile-time after unroll
            if (dy >= 0 && dy <= 14) {
                const int wr = (dy <= 7) ? dy : 14 - dy;
                const u64* kw = &sk[wr * 8];
                ulonglong2 w01 = *reinterpret_cast<const ulonglong2*>(kw + 0);
                ulonglong2 w23 = *reinterpret_cast<const ulonglong2*>(kw + 2);
                ulonglong2 w45 = *reinterpret_cast<const ulonglong2*>(kw + 4);
                ulonglong2 w67 = *reinterpret_cast<const ulonglong2*>(kw + 6);
                fma2(acc0[r], h0[0], w01.x);  fma2(acc1[r], h1[0], w01.x);
                fma2(acc0[r], h0[1], w01.y);  fma2(acc1[r], h1[1], w01.y);
                fma2(acc0[r], h0[2], w23.x);  fma2(acc1[r], h1[2], w23.x);
                fma2(acc0[r], h0[3], w23.y);  fma2(acc1[r], h1[3], w23.y);
                fma2(acc0[r], h0[4], w45.x);  fma2(acc1[r], h1[4], w45.x);
                fma2(acc0[r], h0[5], w45.y);  fma2(acc1[r], h1[5], w45.y);
                fma2(acc0[r], h0[6], w67.x);  fma2(acc1[r], h1[6], w67.x);
                fma2(acc0[r], h0[7], w67.y);  fma2(acc1[r], h1[7], w67.y);
            }
        }
    }

    // Fused roll: out[b, y, (x + s) & 1023] = conv[b, y, x].
    #pragma unroll
    for (int r = 0; r < 4; ++r) {
        const int y = y0 + r;
        const int s = shifts[b * IMG_H + y];
        float* orow = out + ((size_t)b * IMG_H + y) * IMG_W;
        float lo0, hi0, lo1, hi1;
        unpack2(acc0[r], lo0, hi0);
        unpack2(acc1[r], lo1, hi1);
        int c0 = (x0 + s) & (IMG_W - 1);
        int c1 = (x0 + 2 + s) & (IMG_W - 1);
        if ((s & 1) == 0) {
            // even shift: c0,c1 even -> aligned float2, never straddle the wrap
            *reinterpret_cast<float2*>(orow + c0) = make_float2(lo0, hi0);
            *reinterpret_cast<float2*>(orow + c1) = make_float2(lo1, hi1);
        } else {
            orow[c0] = lo0;
            orow[(c0 + 1) & (IMG_W - 1)] = hi0;
            orow[c1] = lo1;
            orow[(c1 + 1) & (IMG_W - 1)] = hi1;
        }
    }
}

extern "C" void kernel_launch(void* const* d_in, const int* in_sizes, int n_in,
                              void* d_out, int out_size) {
    const float* img = nullptr;
    const float* kern = nullptr;
    const int*   shifts = nullptr;
    for (int i = 0; i < n_in; ++i) {
        if (in_sizes[i] == NB * IMG_H * IMG_W)      img    = (const float*)d_in[i];
        else if (in_sizes[i] == KS * KS)            kern   = (const float*)d_in[i];
        else if (in_sizes[i] == NB * IMG_H)         shifts = (const int*)d_in[i];
    }
    cudaFuncSetAttribute(stem_conv_roll,
                         cudaFuncAttributeMaxDynamicSharedMemorySize, SMEM_BYTES);
    dim3 grid(IMG_W / 256, IMG_H / 16, NB);
    stem_conv_roll<<<grid, 256, SMEM_BYTES>>>(img, kern, shifts, (float*)d_out);
}

// round 9
// speedup vs baseline: 1.2061x; 1.2061x over previous
#include <cuda_runtime.h>
#include <cuda_bf16.h>

#define IMG_W 1024
#define IMG_H 1024
#define KS 15
#define NB 32

// Input tile staged in smem: x covers [bx*256-8, bx*256+264) = 272 floats,
// y covers [by*32-7, by*32+39) = 46 rows. Zero-padded outside the image.
#define TILE_W 272
#define TILE_H 30 /* unused */
#define TILE_HH 46
#define SMEM_BYTES (512 + TILE_W * TILE_HH * 4)

typedef unsigned long long u64;

// ---- packed fp32x2 helpers (Blackwell, PTX-only) ----
__device__ __forceinline__ u64 pack2(float lo, float hi) {
    u64 r;
    asm("mov.b64 %0, {%1, %2};" : "=l"(r) : "f"(lo), "f"(hi));
    return r;
}
__device__ __forceinline__ void unpack2(u64 v, float& lo, float& hi) {
    asm("mov.b64 {%0, %1}, %2;" : "=f"(lo), "=f"(hi) : "l"(v));
}
__device__ __forceinline__ void fma2(u64& d, u64 a, u64 b) {
    asm("fma.rn.f32x2 %0, %1, %2, %3;" : "=l"(d) : "l"(a), "l"(b), "l"(d));
}
__device__ __forceinline__ u64 add2(u64 a, u64 b) {
    u64 r;
    asm("add.rn.f32x2 %0, %1, %2;" : "=l"(r) : "l"(a), "l"(b));
    return r;
}
// (hi(a), lo(b)) — odd-offset pair from two aligned pairs
__device__ __forceinline__ u64 mk_t(u64 a, u64 b) {
    float alo, ahi, blo, bhi;
    unpack2(a, alo, ahi);
    unpack2(b, blo, bhi);
    return pack2(ahi, blo);
}
__device__ __forceinline__ unsigned smem_u32(const void* p) {
    unsigned r;
    asm("{ .reg .u64 t; cvta.to.shared.u64 t, %1; cvt.u32.u64 %0, t; }" : "=r"(r) : "l"(p));
    return r;
}

// Thread: 4 px (two f32x2 pairs) x 8 output rows. Block 256 thr = 8 warps:
// 2 in x, 4 in y. Block tile: 256 px * 32 rows. Grid (4, 32, 32).
// Weights (dx+dy folded Airy symmetry): 8 rows x 8 (w,w) pairs in smem;
// each weight fetch is applied to BOTH dy-symmetric output rows.
__global__ __launch_bounds__(256, 2) void stem_conv_roll(
    const float* __restrict__ in, const float* __restrict__ kern,
    const int* __restrict__ shifts, float* __restrict__ out)
{
    extern __shared__ char dynsmem[];
    u64*   sk  = reinterpret_cast<u64*>(dynsmem);          // 64 * 8B = 512B
    float* sIn = reinterpret_cast<float*>(dynsmem + 512);  // [TILE_HH][TILE_W]

    const int tid = threadIdx.x;
    const int b   = blockIdx.z;
    const float* img = in + (size_t)b * (IMG_H * IMG_W);

    // Folded weights: sk[wr*8 + e] = (w,w), w = k[wr][7+e], wr = 0..7.
    if (tid < 64) {
        int wr = tid >> 3, e = tid & 7;
        float w = kern[wr * KS + 7 + e];
        sk[tid] = pack2(w, w);
    }

    // ---- Stage input tile via cp.async, zero-filled outside the image.
    // Every partially-OOB float4 in this geometry is fully OOB (W,offsets mult 4),
    // so src_size=0 zfill handles all padding.
    {
        const int gxb = blockIdx.x * 256 - 8;
        const int gyb = blockIdx.y * 32 - 7;
        const unsigned sbase = smem_u32(dynsmem) + 512;
        for (int idx = tid; idx < TILE_HH * (TILE_W / 4); idx += 256) {
            const int ry  = idx / (TILE_W / 4);
            const int rx4 = idx - ry * (TILE_W / 4);
            const int gy  = gyb + ry;
            const int gx  = gxb + rx4 * 4;
            const bool ok = (gy >= 0) && (gy < IMG_H) && (gx >= 0) && (gx <= IMG_W - 4);
            const float* src = ok ? (img + (size_t)gy * IMG_W + gx) : img;
            const unsigned dst = sbase + (unsigned)(ry * TILE_W + rx4 * 4) * 4u;
            const int sz = ok ? 16 : 0;
            asm volatile("cp.async.ca.shared.global [%0], [%1], 16, %2;"
                         :: "r"(dst), "l"(src), "r"(sz));
        }
        asm volatile("cp.async.commit_group;\n\tcp.async.wait_group 0;" ::: "memory");
    }
    __syncthreads();

    const int lane = tid & 31;
    const int warp = tid >> 5;
    const int wx = warp & 1;
    const int wy = warp >> 1;
    const int xl = wx * 128 + lane * 4;       // local x of first px (mult of 4)
    const int x0 = blockIdx.x * 256 + xl;
    const int y0 = blockIdx.y * 32 + wy * 8;

    u64 acc0[8], acc1[8];
    #pragma unroll
    for (int r = 0; r < 8; ++r) { acc0[r] = 0ull; acc1[r] = 0ull; }

    const float* tbase = sIn + wy * 8 * TILE_W + xl;

    #pragma unroll
    for (int g = 0; g < 22; ++g) {
        const ulonglong2* tr2 = reinterpret_cast<const ulonglong2*>(tbase + g * TILE_W);
        // Aligned pairs s[j] = (ga[2j], ga[2j+1]) come straight from 16B loads.
        ulonglong2 p0 = tr2[0], p1 = tr2[1], p2 = tr2[2], p3 = tr2[3], p4 = tr2[4];
        u64 s0 = p0.x, s1 = p0.y, s2 = p1.x, s3 = p1.y, s4 = p2.x,
            s5 = p2.y, s6 = p3.x, s7 = p3.y, s8 = p4.x;
        // Odd-offset pairs t[j] = (ga[2j+1], ga[2j+2]), shared by h0 and h1.
        u64 t0 = mk_t(s0, s1), t1 = mk_t(s1, s2), t2 = mk_t(s2, s3),
            t3 = mk_t(s3, s4), t4 = mk_t(s4, s5), t5 = mk_t(s5, s6),
            t6 = mk_t(s6, s7), t7 = mk_t(s7, s8);
        u64 t8 = mk_t(s8, tr2[4].y);

        // Horizontal folds, all as packed add2 (1 fma-slot each).
        u64 h0[8], h1[8];
        h0[0] = s4;
        h0[1] = add2(t3, t4);
        h0[2] = add2(s3, s5);
        h0[3] = add2(t2, t5);
        h0[4] = add2(s2, s6);
        h0[5] = add2(t1, t6);
        h0[6] = add2(s1, s7);
        h0[7] = add2(t0, t7);

        h1[0] = s5;
        h1[1] = add2(t4, t5);
        h1[2] = add2(s4, s6);
        h1[3] = add2(t3, t6);
        h1[4] = add2(s3, s7);
        h1[5] = add2(t2, t7);
        h1[6] = add2(s2, s8);
        h1[7] = add2(t1, t8);

        // Weight row wr serves BOTH dy-symmetric output rows:
        //   r1 = g - wr (dy = wr), r2 = g - 14 + wr (dy = 14 - wr).
        #pragma unroll
        for (int wr = 0; wr < 8; ++wr) {
            const int r1 = g - wr;
            const int r2 = g - 14 + wr;
            const bool u1 = (r1 >= 0) && (r1 < 8);
            const bool u2 = (wr < 7) && (r2 >= 0) && (r2 < 8);
            if (u1 || u2) {
                const u64* kw = &sk[wr * 8];
                ulonglong2 w01 = *reinterpret_cast<const ulonglong2*>(kw + 0);
                ulonglong2 w23 = *reinterpret_cast<const ulonglong2*>(kw + 2);
                ulonglong2 w45 = *reinterpret_cast<const ulonglong2*>(kw + 4);
                ulonglong2 w67 = *reinterpret_cast<const ulonglong2*>(kw + 6);
                if (u1) {
                    fma2(acc0[r1], h0[0], w01.x);  fma2(acc1[r1], h1[0], w01.x);
                    fma2(acc0[r1], h0[1], w01.y);  fma2(acc1[r1], h1[1], w01.y);
                    fma2(acc0[r1], h0[2], w23.x);  fma2(acc1[r1], h1[2], w23.x);
                    fma2(acc0[r1], h0[3], w23.y);  fma2(acc1[r1], h1[3], w23.y);
                    fma2(acc0[r1], h0[4], w45.x);  fma2(acc1[r1], h1[4], w45.x);
                    fma2(acc0[r1], h0[5], w45.y);  fma2(acc1[r1], h1[5], w45.y);
                    fma2(acc0[r1], h0[6], w67.x);  fma2(acc1[r1], h1[6], w67.x);
                    fma2(acc0[r1], h0[7], w67.y);  fma2(acc1[r1], h1[7], w67.y);
                }
                if (u2) {
                    fma2(acc0[r2], h0[0], w01.x);  fma2(acc1[r2], h1[0], w01.x);
                    fma2(acc0[r2], h0[1], w01.y);  fma2(acc1[r2], h1[1], w01.y);
                    fma2(acc0[r2], h0[2], w23.x);  fma2(acc1[r2], h1[2], w23.x);
                    fma2(acc0[r2], h0[3], w23.y);  fma2(acc1[r2], h1[3], w23.y);
                    fma2(acc0[r2], h0[4], w45.x);  fma2(acc1[r2], h1[4], w45.x);
                    fma2(acc0[r2], h0[5], w45.y);  fma2(acc1[r2], h1[5], w45.y);
                    fma2(acc0[r2], h0[6], w67.x);  fma2(acc1[r2], h1[6], w67.x);
                    fma2(acc0[r2], h0[7], w67.y);  fma2(acc1[r2], h1[7], w67.y);
                }
            }
        }
    }

    // Fused roll: out[b, y, (x + s) & 1023] = conv[b, y, x].
    #pragma unroll
    for (int r = 0; r < 8; ++r) {
        const int y = y0 + r;
        const int s = shifts[b * IMG_H + y];
        float* orow = out + ((size_t)b * IMG_H + y) * IMG_W;
        float lo0, hi0, lo1, hi1;
        unpack2(acc0[r], lo0, hi0);
        unpack2(acc1[r], lo1, hi1);
        int c0 = (x0 + s) & (IMG_W - 1);
        int c1 = (x0 + 2 + s) & (IMG_W - 1);
        if ((s & 1) == 0) {
            // even shift: c0,c1 even -> aligned float2, never straddle the wrap
            *reinterpret_cast<float2*>(orow + c0) = make_float2(lo0, hi0);
            *reinterpret_cast<float2*>(orow + c1) = make_float2(lo1, hi1);
        } else {
            orow[c0] = lo0;
            orow[(c0 + 1) & (IMG_W - 1)] = hi0;
            orow[c1] = lo1;
            orow[(c1 + 1) & (IMG_W - 1)] = hi1;
        }
    }
}

extern "C" void kernel_launch(void* const* d_in, const int* in_sizes, int n_in,
                              void* d_out, int out_size) {
    const float* img = nullptr;
    const float* kern = nullptr;
    const int*   shifts = nullptr;
    for (int i = 0; i < n_in; ++i) {
        if (in_sizes[i] == NB * IMG_H * IMG_W)      img    = (const float*)d_in[i];
        else if (in_sizes[i] == KS * KS)            kern   = (const float*)d_in[i];
        else if (in_sizes[i] == NB * IMG_H)         shifts = (const int*)d_in[i];
    }
    cudaFuncSetAttribute(stem_conv_roll,
                         cudaFuncAttributeMaxDynamicSharedMemorySize, SMEM_BYTES);
    dim3 grid(IMG_W / 256, IMG_H / 32, NB);
    stem_conv_roll<<<grid, 256, SMEM_BYTES>>>(img, kern, shifts, (float*)d_out);
}

// round 10
// speedup vs baseline: 1.2141x; 1.0066x over previous
#include <cuda_runtime.h>
#include <cuda_bf16.h>

#define IMG_W 1024
#define IMG_H 1024
#define KS 15
#define NB 32

// Input tile staged in smem: x covers [bx*256-8, bx*256+264) = 272 floats,
// y covers [by*32-7, by*32+39) = 46 rows. Zero-padded outside the image.
#define TILE_W 272
#define TILE_HH 46
#define SMEM_BYTES (512 + TILE_W * TILE_HH * 4)

typedef unsigned long long u64;

// ---- packed fp32x2 helpers (Blackwell, PTX-only) ----
__device__ __forceinline__ u64 pack2(float lo, float hi) {
    u64 r;
    asm("mov.b64 %0, {%1, %2};" : "=l"(r) : "f"(lo), "f"(hi));
    return r;
}
__device__ __forceinline__ void unpack2(u64 v, float& lo, float& hi) {
    asm("mov.b64 {%0, %1}, %2;" : "=f"(lo), "=f"(hi) : "l"(v));
}
__device__ __forceinline__ void fma2(u64& d, u64 a, u64 b) {
    asm("fma.rn.f32x2 %0, %1, %2, %3;" : "=l"(d) : "l"(a), "l"(b), "l"(d));
}
__device__ __forceinline__ u64 add2(u64 a, u64 b) {
    u64 r;
    asm("add.rn.f32x2 %0, %1, %2;" : "=l"(r) : "l"(a), "l"(b));
    return r;
}
// (hi(a), lo(b)) — odd-offset pair from two aligned pairs
__device__ __forceinline__ u64 mk_t(u64 a, u64 b) {
    float alo, ahi, blo, bhi;
    unpack2(a, alo, ahi);
    unpack2(b, blo, bhi);
    return pack2(ahi, blo);
}
__device__ __forceinline__ unsigned smem_u32(const void* p) {
    unsigned r;
    asm("{ .reg .u64 t; cvta.to.shared.u64 t, %1; cvt.u32.u64 %0, t; }" : "=r"(r) : "l"(p));
    return r;
}

// Thread: 4 px (two f32x2 pairs) x 8 output rows. Block 256 thr = 8 warps:
// 2 in x, 4 in y. Block tile: 256 px * 32 rows. Grid (4, 32, 32).
// Weights (dx+dy folded Airy symmetry): 8 rows x 8 (w,w) pairs in smem;
// each weight fetch serves BOTH dy-symmetric output rows.
// The e-dimension is processed in TWO passes (e=0..3, e=4..7) per g to halve
// the live h-register footprint and give ptxas headroom to hoist LDS.
__global__ __launch_bounds__(256, 2) void stem_conv_roll(
    const float* __restrict__ in, const float* __restrict__ kern,
    const int* __restrict__ shifts, float* __restrict__ out)
{
    extern __shared__ char dynsmem[];
    u64*   sk  = reinterpret_cast<u64*>(dynsmem);          // 64 * 8B = 512B
    float* sIn = reinterpret_cast<float*>(dynsmem + 512);  // [TILE_HH][TILE_W]

    const int tid = threadIdx.x;
    const int b   = blockIdx.z;
    const float* img = in + (size_t)b * (IMG_H * IMG_W);

    // ---- Stage input tile via cp.async, zero-filled outside the image.
    // Every partially-OOB float4 in this geometry is fully OOB, so
    // src_size=0 zfill handles all padding.
    {
        const int gxb = blockIdx.x * 256 - 8;
        const int gyb = blockIdx.y * 32 - 7;
        const unsigned sbase = smem_u32(dynsmem) + 512;
        for (int idx = tid; idx < TILE_HH * (TILE_W / 4); idx += 256) {
            const int ry  = idx / (TILE_W / 4);
            const int rx4 = idx - ry * (TILE_W / 4);
            const int gy  = gyb + ry;
            const int gx  = gxb + rx4 * 4;
            const bool ok = (gy >= 0) && (gy < IMG_H) && (gx >= 0) && (gx <= IMG_W - 4);
            const float* src = ok ? (img + (size_t)gy * IMG_W + gx) : img;
            const unsigned dst = sbase + (unsigned)(ry * TILE_W + rx4 * 4) * 4u;
            const int sz = ok ? 16 : 0;
            asm volatile("cp.async.ca.shared.global [%0], [%1], 16, %2;"
                         :: "r"(dst), "l"(src), "r"(sz));
        }
    }

    // Folded weights (overlaps the async staging): sk[wr*8+e] = (w,w),
    // w = k[wr][7+e], wr = 0..7.
    if (tid < 64) {
        int wr = tid >> 3, e = tid & 7;
        float w = kern[wr * KS + 7 + e];
        sk[tid] = pack2(w, w);
    }
    asm volatile("cp.async.commit_group;\n\tcp.async.wait_group 0;" ::: "memory");
    __syncthreads();

    const int lane = tid & 31;
    const int warp = tid >> 5;
    const int wx = warp & 1;
    const int wy = warp >> 1;
    const int xl = wx * 128 + lane * 4;       // local x of first px (mult of 4)
    const int x0 = blockIdx.x * 256 + xl;
    const int y0 = blockIdx.y * 32 + wy * 8;

    u64 acc0[8], acc1[8];
    #pragma unroll
    for (int r = 0; r < 8; ++r) { acc0[r] = 0ull; acc1[r] = 0ull; }

    const float* tbase = sIn + wy * 8 * TILE_W + xl;

    #pragma unroll
    for (int g = 0; g < 22; ++g) {
        const ulonglong2* tr2 = reinterpret_cast<const ulonglong2*>(tbase + g * TILE_W);
        ulonglong2 p0 = tr2[0], p1 = tr2[1], p2 = tr2[2], p3 = tr2[3], p4 = tr2[4];
        u64 s0 = p0.x, s1 = p0.y, s2 = p1.x, s3 = p1.y, s4 = p2.x,
            s5 = p2.y, s6 = p3.x, s7 = p3.y, s8 = p4.x, s9 = p4.y;

        // ---------- Pass A: e = 0..3 (weights w01, w23) ----------
        {
            u64 t2 = mk_t(s2, s3), t3 = mk_t(s3, s4), t4 = mk_t(s4, s5),
                t5 = mk_t(s5, s6), t6 = mk_t(s6, s7);
            u64 ha0[4], ha1[4];
            ha0[0] = s4;
            ha0[1] = add2(t3, t4);
            ha0[2] = add2(s3, s5);
            ha0[3] = add2(t2, t5);
            ha1[0] = s5;
            ha1[1] = add2(t4, t5);
            ha1[2] = add2(s4, s6);
            ha1[3] = add2(t3, t6);

            #pragma unroll
            for (int wr = 0; wr < 8; ++wr) {
                const int r1 = g - wr;
                const int r2 = g - 14 + wr;
                const bool u1 = (r1 >= 0) && (r1 < 8);
                const bool u2 = (wr < 7) && (r2 >= 0) && (r2 < 8);
                if (u1 || u2) {
                    const u64* kw = &sk[wr * 8];
                    ulonglong2 w01 = *reinterpret_cast<const ulonglong2*>(kw + 0);
                    ulonglong2 w23 = *reinterpret_cast<const ulonglong2*>(kw + 2);
                    if (u1) {
                        fma2(acc0[r1], ha0[0], w01.x);  fma2(acc1[r1], ha1[0], w01.x);
                        fma2(acc0[r1], ha0[1], w01.y);  fma2(acc1[r1], ha1[1], w01.y);
                        fma2(acc0[r1], ha0[2], w23.x);  fma2(acc1[r1], ha1[2], w23.x);
                        fma2(acc0[r1], ha0[3], w23.y);  fma2(acc1[r1], ha1[3], w23.y);
                    }
                    if (u2) {
                        fma2(acc0[r2], ha0[0], w01.x);  fma2(acc1[r2], ha1[0], w01.x);
                        fma2(acc0[r2], ha0[1], w01.y);  fma2(acc1[r2], ha1[1], w01.y);
                        fma2(acc0[r2], ha0[2], w23.x);  fma2(acc1[r2], ha1[2], w23.x);
                        fma2(acc0[r2], ha0[3], w23.y);  fma2(acc1[r2], ha1[3], w23.y);
                    }
                }
            }
        }

        // ---------- Pass B: e = 4..7 (weights w45, w67) ----------
        {
            u64 t0 = mk_t(s0, s1), t1 = mk_t(s1, s2), t2 = mk_t(s2, s3),
                t6 = mk_t(s6, s7), t7 = mk_t(s7, s8), t8 = mk_t(s8, s9);
            u64 hb0[4], hb1[4];
            hb0[0] = add2(s2, s6);
            hb0[1] = add2(t1, t6);
            hb0[2] = add2(s1, s7);
            hb0[3] = add2(t0, t7);
            hb1[0] = add2(s3, s7);
            hb1[1] = add2(t2, t7);
            hb1[2] = add2(s2, s8);
            hb1[3] = add2(t1, t8);

            #pragma unroll
            for (int wr = 0; wr < 8; ++wr) {
                const int r1 = g - wr;
                const int r2 = g - 14 + wr;
                const bool u1 = (r1 >= 0) && (r1 < 8);
                const bool u2 = (wr < 7) && (r2 >= 0) && (r2 < 8);
                if (u1 || u2) {
                    const u64* kw = &sk[wr * 8];
                    ulonglong2 w45 = *reinterpret_cast<const ulonglong2*>(kw + 4);
                    ulonglong2 w67 = *reinterpret_cast<const ulonglong2*>(kw + 6);
                    if (u1) {
                        fma2(acc0[r1], hb0[0], w45.x);  fma2(acc1[r1], hb1[0], w45.x);
                        fma2(acc0[r1], hb0[1], w45.y);  fma2(acc1[r1], hb1[1], w45.y);
                        fma2(acc0[r1], hb0[2], w67.x);  fma2(acc1[r1], hb1[2], w67.x);
                        fma2(acc0[r1], hb0[3], w67.y);  fma2(acc1[r1], hb1[3], w67.y);
                    }
                    if (u2) {
                        fma2(acc0[r2], hb0[0], w45.x);  fma2(acc1[r2], hb1[0], w45.x);
                        fma2(acc0[r2], hb0[1], w45.y);  fma2(acc1[r2], hb1[1], w45.y);
                        fma2(acc0[r2], hb0[2], w67.x);  fma2(acc1[r2], hb1[2], w67.x);
                        fma2(acc0[r2], hb0[3], w67.y);  fma2(acc1[r2], hb1[3], w67.y);
                    }
                }
            }
        }
    }

    // Fused roll: out[b, y, (x + s) & 1023] = conv[b, y, x].
    #pragma unroll
    for (int r = 0; r < 8; ++r) {
        const int y = y0 + r;
        const int s = shifts[b * IMG_H + y];
        float* orow = out + ((size_t)b * IMG_H + y) * IMG_W;
        float lo0, hi0, lo1, hi1;
        unpack2(acc0[r], lo0, hi0);
        unpack2(acc1[r], lo1, hi1);
        int c0 = (x0 + s) & (IMG_W - 1);
        int c1 = (x0 + 2 + s) & (IMG_W - 1);
        if ((s & 1) == 0) {
            // even shift: c0,c1 even -> aligned float2, never straddle the wrap
            *reinterpret_cast<float2*>(orow + c0) = make_float2(lo0, hi0);
            *reinterpret_cast<float2*>(orow + c1) = make_float2(lo1, hi1);
        } else {
            orow[c0] = lo0;
            orow[(c0 + 1) & (IMG_W - 1)] = hi0;
            orow[c1] = lo1;
            orow[(c1 + 1) & (IMG_W - 1)] = hi1;
        }
    }
}

extern "C" void kernel_launch(void* const* d_in, const int* in_sizes, int n_in,
                              void* d_out, int out_size) {
    const float* img = nullptr;
    const float* kern = nullptr;
    const int*   shifts = nullptr;
    for (int i = 0; i < n_in; ++i) {
        if (in_sizes[i] == NB * IMG_H * IMG_W)      img    = (const float*)d_in[i];
        else if (in_sizes[i] == KS * KS)            kern   = (const float*)d_in[i];
        else if (in_sizes[i] == NB * IMG_H)         shifts = (const int*)d_in[i];
    }
    cudaFuncSetAttribute(stem_conv_roll,
                         cudaFuncAttributeMaxDynamicSharedMemorySize, SMEM_BYTES);
    dim3 grid(IMG_W / 256, IMG_H / 32, NB);
    stem_conv_roll<<<grid, 256, SMEM_BYTES>>>(img, kern, shifts, (float*)d_out);
}